// round 1
// baseline (speedup 1.0000x reference)
#include <cuda_runtime.h>

// Problem constants
#define BB   128
#define DD   1024
#define HH1  512
#define HH2  256

// ---------------- scratch (device globals; no allocation allowed) ----------
__device__ float g_c1[BB * HH1];
__device__ float g_s1[BB * HH1];
__device__ float g_c2[BB * HH2];
__device__ float g_s2[BB * HH2];
__device__ float g_c3[BB * HH1];
__device__ float g_s3[BB * HH1];
__device__ float g_M1[(size_t)BB * HH2 * DD];   // 134 MB
__device__ float g_M2[(size_t)BB * HH1 * DD];   // 268 MB

// ---------------- forward pass: one output per thread ----------------------
// C[b,n] = sigmoid( sum_k A[b,k] * W(k,n) + bias[n] )
// transW=1: W element = W[n*K + k];  transW=0: W element = W[k*N + n]
__global__ void fwd_kernel(const float* __restrict__ A,
                           const float* __restrict__ W,
                           const float* __restrict__ bias,
                           float* __restrict__ c_out,
                           float* __restrict__ s_out,
                           float* __restrict__ extra_out,
                           int K, int N, int transW) {
    __shared__ float sA[1024];
    const int b   = blockIdx.y;
    const int tid = threadIdx.x;
    for (int k = tid; k < K; k += 128) sA[k] = A[(size_t)b * K + k];
    __syncthreads();
    const int n = blockIdx.x * 128 + tid;
    float acc = bias[n];
    if (transW) {
        const float* wr = W + (size_t)n * K;
        #pragma unroll 4
        for (int k = 0; k < K; k++) acc += sA[k] * wr[k];
    } else {
        #pragma unroll 4
        for (int k = 0; k < K; k++) acc += sA[k] * W[(size_t)k * N + n];
    }
    const float c = 1.0f / (1.0f + expf(-acc));
    if (c_out)     c_out[(size_t)b * N + n]     = c;
    if (s_out)     s_out[(size_t)b * N + n]     = c * (1.0f - c);
    if (extra_out) extra_out[(size_t)b * N + n] = c;
}

// ---------------- batched scaled GEMM ---------------------------------------
// For each b (blockIdx.z):
//   C_b[m,n] = sum_k Aelem(m,k) * scale[b*K + k] * B_b[k*ldb + n]
// Aelem(m,k) = transA ? A[k*lda + m] : A[m*lda + k]
// C_b = C + b*strideC, row stride ldc.  B_b = B + b*strideB.
// Tile: 128x128x8, 256 threads, 8x8 per thread, FFMA2 (fma.rn.f32x2).
typedef unsigned long long ull;

union F4U { float4 f; ull u[2]; };

__global__ __launch_bounds__(256)
void jgemm(const float* __restrict__ A, const float* __restrict__ Bm,
           const float* __restrict__ scale, float* __restrict__ C,
           int K, int lda, int ldb, int ldc,
           long strideB, long strideC, int transA) {
    __shared__ float sA[8][128];
    __shared__ float sB[8][128];

    const int b  = blockIdx.z;
    const float* __restrict__ Bb = Bm + (size_t)b * strideB;
    const float* __restrict__ sc = scale + (size_t)b * K;
    float* __restrict__ Cb = C + (size_t)b * strideC;

    const int m0  = blockIdx.y * 128;
    const int n0  = blockIdx.x * 128;
    const int tid = threadIdx.x;
    const int tx  = tid & 15;    // 16 cols of threads -> 8 floats each
    const int ty  = tid >> 4;    // 16 rows of threads -> 8 floats each

    ull acc[8][4];
    #pragma unroll
    for (int i = 0; i < 8; i++)
        #pragma unroll
        for (int j = 0; j < 4; j++) acc[i][j] = 0ULL;   // {0.f, 0.f}

    for (int kt = 0; kt < K; kt += 8) {
        if (transA) {
            #pragma unroll
            for (int r = 0; r < 4; r++) {
                int idx = tid + r * 256;
                int k = idx >> 7, m = idx & 127;          // coalesced along m
                sA[k][m] = A[(size_t)(kt + k) * lda + m0 + m] * sc[kt + k];
            }
        } else {
            #pragma unroll
            for (int r = 0; r < 4; r++) {
                int idx = tid + r * 256;
                int m = idx >> 3, k = idx & 7;
                sA[k][m] = A[(size_t)(m0 + m) * lda + kt + k] * sc[kt + k];
            }
        }
        #pragma unroll
        for (int r = 0; r < 4; r++) {
            int idx = tid + r * 256;
            int k = idx >> 7, n = idx & 127;              // coalesced along n
            sB[k][n] = Bb[(size_t)(kt + k) * ldb + n0 + n];
        }
        __syncthreads();

        #pragma unroll
        for (int k = 0; k < 8; k++) {
            F4U b0, b1;
            b0.f = *(const float4*)&sB[k][tx * 8];
            b1.f = *(const float4*)&sB[k][tx * 8 + 4];
            ull bb[4] = { b0.u[0], b0.u[1], b1.u[0], b1.u[1] };

            float4 a0 = *(const float4*)&sA[k][ty * 8];
            float4 a1 = *(const float4*)&sA[k][ty * 8 + 4];
            float av[8] = { a0.x, a0.y, a0.z, a0.w, a1.x, a1.y, a1.z, a1.w };

            #pragma unroll
            for (int i = 0; i < 8; i++) {
                ull aa;
                asm("mov.b64 %0, {%1, %1};" : "=l"(aa) : "f"(av[i]));
                #pragma unroll
                for (int j = 0; j < 4; j++) {
                    asm("fma.rn.f32x2 %0, %1, %2, %3;"
                        : "=l"(acc[i][j])
                        : "l"(aa), "l"(bb[j]), "l"(acc[i][j]));
                }
            }
        }
        __syncthreads();
    }

    #pragma unroll
    for (int i = 0; i < 8; i++) {
        ull* crow = (ull*)(Cb + (size_t)(m0 + ty * 8 + i) * ldc + n0 + tx * 8);
        #pragma unroll
        for (int j = 0; j < 4; j++) crow[j] = acc[i][j];
    }
}

// ---------------- launcher ---------------------------------------------------
extern "C" void kernel_launch(void* const* d_in, const int* in_sizes, int n_in,
                              void* d_out, int out_size) {
    const float* x   = (const float*)d_in[0];  // [128,1024]
    const float* W1  = (const float*)d_in[1];  // [512,1024]
    const float* b1  = (const float*)d_in[2];  // [512]
    const float* W2  = (const float*)d_in[3];  // [256,512]
    const float* b2  = (const float*)d_in[4];  // [256]
    const float* b3  = (const float*)d_in[5];  // [512]
    const float* b_r = (const float*)d_in[6];  // [1024]

    float* out       = (float*)d_out;
    float* out_rec   = out;                          // [128,1024]
    float* out_c2    = out + (size_t)BB * DD;        // [128,256]
    float* out_jac   = out_c2 + (size_t)BB * HH2;    // [D, B, D] flat layout

    float *c1, *s1, *c2, *s2, *c3, *s3, *M1, *M2;
    cudaGetSymbolAddress((void**)&c1, g_c1);
    cudaGetSymbolAddress((void**)&s1, g_s1);
    cudaGetSymbolAddress((void**)&c2, g_c2);
    cudaGetSymbolAddress((void**)&s2, g_s2);
    cudaGetSymbolAddress((void**)&c3, g_c3);
    cudaGetSymbolAddress((void**)&s3, g_s3);
    cudaGetSymbolAddress((void**)&M1, g_M1);
    cudaGetSymbolAddress((void**)&M2, g_M2);

    // -------- forward pass --------
    // c1 = sig(x @ W1^T + b1)
    fwd_kernel<<<dim3(HH1 / 128, BB), 128>>>(x, W1, b1, c1, s1, nullptr,
                                             DD, HH1, 1);
    // c2 = sig(c1 @ W2^T + b2)   (also written to output)
    fwd_kernel<<<dim3(HH2 / 128, BB), 128>>>(c1, W2, b2, c2, s2, out_c2,
                                             HH1, HH2, 1);
    // c3 = sig(c2 @ W2 + b3)
    fwd_kernel<<<dim3(HH1 / 128, BB), 128>>>(c2, W2, b3, c3, s3, nullptr,
                                             HH2, HH1, 0);
    // recover = sig(c3 @ W1 + b_r)  (straight to output)
    fwd_kernel<<<dim3(DD / 128, BB), 128>>>(c3, W1, b_r, out_rec, nullptr, nullptr,
                                            HH1, DD, 0);

    // -------- Jacobian chain --------
    // Step A: M1[b,e,d] = sum_h W2[e,h] * s3[b,h] * W1[h,d]        [B,256,1024]
    jgemm<<<dim3(DD / 128, HH2 / 128, BB), 256>>>(
        W2, W1, s3, M1,
        /*K=*/HH1, /*lda=*/HH1, /*ldb=*/DD, /*ldc=*/DD,
        /*strideB=*/0L, /*strideC=*/(long)HH2 * DD, /*transA=*/0);

    // Step B: M2[b,h,d] = sum_e W2[e,h] * s2[b,e] * M1[b,e,d]      [B,512,1024]
    jgemm<<<dim3(DD / 128, HH1 / 128, BB), 256>>>(
        W2, M1, s2, M2,
        /*K=*/HH2, /*lda=*/HH1, /*ldb=*/DD, /*ldc=*/DD,
        /*strideB=*/(long)HH2 * DD, /*strideC=*/(long)HH1 * DD, /*transA=*/1);

    // Step C: Jst[b,d,e] = sum_h W1[h,d] * s1[b,h] * M2[b,h,e]
    // Written directly in the reference's permuted flat layout:
    //   offset(b,d,e) = d*(B*D) + b*D + e   -> ldc = B*D, strideC = D
    jgemm<<<dim3(DD / 128, DD / 128, BB), 256>>>(
        W1, M2, s1, out_jac,
        /*K=*/HH1, /*lda=*/DD, /*ldb=*/DD, /*ldc=*/BB * DD,
        /*strideB=*/(long)HH1 * DD, /*strideC=*/(long)DD, /*transA=*/1);
}

// round 3
// speedup vs baseline: 2.9219x; 2.9219x over previous
#include <cuda_runtime.h>
#include <cuda_bf16.h>
#include <cstdint>

#define BB   128
#define DD   1024
#define HH1  512
#define HH2  256

typedef unsigned int u32;
typedef unsigned long long u64;

// ---------------- scratch (device globals; no allocation allowed) ----------
__device__ float g_c1[BB * HH1];
__device__ float g_s1[BB * HH1];
__device__ float g_c2[BB * HH2];
__device__ float g_s2[BB * HH2];
__device__ float g_c3[BB * HH1];
__device__ float g_s3[BB * HH1];
__device__ __nv_bfloat16 g_W1Thi[DD * HH1];          // W1^T hi  [1024,512]
__device__ __nv_bfloat16 g_W1Tlo[DD * HH1];          // W1^T lo
__device__ float         g_W2T[HH1 * HH2];           // W2^T fp32 [512,256]
__device__ __nv_bfloat16 g_M1hi[(size_t)BB * DD * HH2];  // M1' hi [b][1024,256]
__device__ __nv_bfloat16 g_M1lo[(size_t)BB * DD * HH2];  // M1' lo
__device__ float         g_M2[(size_t)BB * DD * HH1];    // M2' fp32 [b][1024,512]

// ---------------- helpers ----------------------------------------------------
__device__ __forceinline__ u32 smem_u32(const void* p) {
    u32 a;
    asm("{ .reg .u64 t; cvta.to.shared.u64 t, %1; cvt.u32.u64 %0, t; }"
        : "=r"(a) : "l"(p));
    return a;
}

#define STS128(ad, v) \
    asm volatile("st.shared.v4.b32 [%0], {%1, %2, %3, %4};" \
                 :: "r"(ad), "r"((v).x), "r"((v).y), "r"((v).z), "r"((v).w) : "memory")

__device__ __forceinline__ void ldsm4(u32* r, u32 addr) {
    asm volatile("ldmatrix.sync.aligned.m8n8.x4.shared.b16 {%0,%1,%2,%3}, [%4];"
                 : "=r"(r[0]), "=r"(r[1]), "=r"(r[2]), "=r"(r[3]) : "r"(addr));
}

__device__ __forceinline__ void mma_bf16(float* c, const u32* a, const u32* b) {
    asm volatile("mma.sync.aligned.m16n8k16.row.col.f32.bf16.bf16.f32 "
                 "{%0,%1,%2,%3}, {%4,%5,%6,%7}, {%8,%9}, {%0,%1,%2,%3};"
                 : "+f"(c[0]), "+f"(c[1]), "+f"(c[2]), "+f"(c[3])
                 : "r"(a[0]), "r"(a[1]), "r"(a[2]), "r"(a[3]),
                   "r"(b[0]), "r"(b[1]));
}

// bf16 split: hi = rn(p) (returned as bf16 bits), lo = p - hi (exact fp32)
__device__ __forceinline__ u32 split1(float p, float& lo) {
    u32 u = __float_as_uint(p);
    u32 r = (u + 0x7FFFu + ((u >> 16) & 1u)) & 0xFFFF0000u;
    lo = p - __uint_as_float(r);
    return r >> 16;
}
__device__ __forceinline__ u32 bf16rn(float p) {
    u32 u = __float_as_uint(p);
    return (u + 0x7FFFu + ((u >> 16) & 1u)) >> 16;
}

// ---------------- forward pass -----------------------------------------------
__global__ void fwd_kernel(const float* __restrict__ A,
                           const float* __restrict__ W,
                           const float* __restrict__ bias,
                           float* __restrict__ c_out,
                           float* __restrict__ s_out,
                           float* __restrict__ extra_out,
                           int K, int N, int transW) {
    __shared__ float sA[1024];
    const int b   = blockIdx.y;
    const int tid = threadIdx.x;
    for (int k = tid; k < K; k += 128) sA[k] = A[(size_t)b * K + k];
    __syncthreads();
    const int n = blockIdx.x * 128 + tid;
    float a0 = 0.f, a1 = 0.f, a2 = 0.f, a3 = 0.f;
    if (transW) {
        const float* wr = W + (size_t)n * K;
        #pragma unroll 2
        for (int k = 0; k < K; k += 4) {
            a0 += sA[k]     * wr[k];
            a1 += sA[k + 1] * wr[k + 1];
            a2 += sA[k + 2] * wr[k + 2];
            a3 += sA[k + 3] * wr[k + 3];
        }
    } else {
        #pragma unroll 2
        for (int k = 0; k < K; k += 4) {
            a0 += sA[k]     * W[(size_t)k * N + n];
            a1 += sA[k + 1] * W[(size_t)(k + 1) * N + n];
            a2 += sA[k + 2] * W[(size_t)(k + 2) * N + n];
            a3 += sA[k + 3] * W[(size_t)(k + 3) * N + n];
        }
    }
    const float acc = bias[n] + ((a0 + a1) + (a2 + a3));
    const float c = 1.0f / (1.0f + expf(-acc));
    if (c_out)     c_out[(size_t)b * N + n]     = c;
    if (s_out)     s_out[(size_t)b * N + n]     = c * (1.0f - c);
    if (extra_out) extra_out[(size_t)b * N + n] = c;
}

// ---------------- one-time transposes ----------------------------------------
__global__ void transpose_split_k(const float* __restrict__ in, int R, int C,
                                  __nv_bfloat16* __restrict__ oh,
                                  __nv_bfloat16* __restrict__ ol) {
    __shared__ float t[32][33];
    const int c0 = blockIdx.x * 32, r0 = blockIdx.y * 32;
    const int tx = threadIdx.x, ty = threadIdx.y;
    #pragma unroll
    for (int i = 0; i < 32; i += 8)
        t[ty + i][tx] = in[(size_t)(r0 + ty + i) * C + c0 + tx];
    __syncthreads();
    #pragma unroll
    for (int i = 0; i < 32; i += 8) {
        float v = t[tx][ty + i];
        size_t o = (size_t)(c0 + ty + i) * R + r0 + tx;
        float lf; u32 h = split1(v, lf);
        ((unsigned short*)oh)[o] = (unsigned short)h;
        ((unsigned short*)ol)[o] = (unsigned short)bf16rn(lf);
    }
}

__global__ void transpose_f32_k(const float* __restrict__ in, int R, int C,
                                float* __restrict__ out) {
    __shared__ float t[32][33];
    const int c0 = blockIdx.x * 32, r0 = blockIdx.y * 32;
    const int tx = threadIdx.x, ty = threadIdx.y;
    #pragma unroll
    for (int i = 0; i < 32; i += 8)
        t[ty + i][tx] = in[(size_t)(r0 + ty + i) * C + c0 + tx];
    __syncthreads();
    #pragma unroll
    for (int i = 0; i < 32; i += 8)
        out[(size_t)(c0 + ty + i) * R + r0 + tx] = t[tx][ty + i];
}

// ---------------- HMMA split-bf16 batched GEMM -------------------------------
// out[b][m, n] = sum_k A[b][m,k] * scale[b,k] * B[b][n,k]
// A: bf16 hi/lo pair in gmem (stride strideA per b; 0 = shared)
// B: fp32 in gmem (stride strideB; 0 = shared), scaled + split at load
// out: fp32 (Cf, ldc, strideC)  OR  bf16 hi/lo pair (Chi/Clo)
//
// Tile 128x128, BK=32, 8 warps (2M x 4N, warp tile 64x32), double-buffered
// SMEM with 80B row pitch (conflict-free ldmatrix), register-staged prefetch.
#define ROWP        80                       // bytes per 32-elem bf16 row
#define MAT_BYTES   (128 * ROWP)             // 10240
#define STAGE_BYTES (4 * MAT_BYTES)          // Ahi, Alo, Bhi, Blo = 40960
#define SMEM_GEMM_BYTES (2 * STAGE_BYTES)    // 81920

template <bool OUT_PAIR>
__global__ void __launch_bounds__(256)
gemm_split(const __nv_bfloat16* __restrict__ Ahi_g,
           const __nv_bfloat16* __restrict__ Alo_g, size_t strideA,
           const float* __restrict__ B_g, size_t strideB,
           const float* __restrict__ sc_g, int K,
           float* __restrict__ Cf,
           __nv_bfloat16* __restrict__ Chi, __nv_bfloat16* __restrict__ Clo,
           size_t ldc, size_t strideC) {
    extern __shared__ char smem[];
    const u32 sb  = smem_u32(smem);
    const int tid = threadIdx.x;
    const int wid = tid >> 5;
    const int lid = tid & 31;
    const int b   = blockIdx.z;
    const int n0  = blockIdx.x * 128;
    const int m0  = blockIdx.y * 128;

    const int m0w = (wid & 1) * 64;          // warp M origin (2 warps in M)
    const int n0w = (wid >> 1) * 32;         // warp N origin (4 warps in N)

    const __nv_bfloat16* Ahi_b = Ahi_g + (size_t)b * strideA;
    const __nv_bfloat16* Alo_b = Alo_g + (size_t)b * strideA;
    const float*         B_b   = B_g + (size_t)b * strideB;
    const float*         sc_b  = sc_g + (size_t)b * K;

    // ---- loader mapping: thread -> (row, 16-elem half of the 32 K slice) ----
    const int r  = tid >> 1;
    const int hs = tid & 1;
    const size_t aRow = (size_t)(m0 + r) * K;
    const size_t bRow = (size_t)(n0 + r) * K;
    const u32 stoff = (u32)r * ROWP + (u32)hs * 32;

    // ---- ldmatrix lane address bases ----
    const int l = lid;
    const u32 a_base = (u32)((m0w + (l & 7) + ((l >> 3) & 1) * 8) * ROWP
                             + ((l >> 4) & 1) * 16);
    const int mt = l >> 3;
    const u32 b_base = (u32)((n0w + ((mt >> 1) & 1) * 8 + (l & 7)) * ROWP
                             + (mt & 1) * 16);

    float acc[4][4][4];
    #pragma unroll
    for (int i = 0; i < 4; i++)
        #pragma unroll
        for (int j = 0; j < 4; j++)
            #pragma unroll
            for (int q = 0; q < 4; q++) acc[i][j][q] = 0.f;

    uint4 pAh[2], pAl[2], pBh[2], pBl[2];

    auto load_regs = [&](int kt) {
        const uint4* ph = (const uint4*)(Ahi_b + aRow + kt) + hs * 2;
        const uint4* pl = (const uint4*)(Alo_b + aRow + kt) + hs * 2;
        pAh[0] = ph[0]; pAh[1] = ph[1];
        pAl[0] = pl[0]; pAl[1] = pl[1];
        const float4* pb = (const float4*)(B_b + bRow + kt) + hs * 4;
        const float4* ps = (const float4*)(sc_b + kt) + hs * 4;
        u32 hw[8], lw[8];
        #pragma unroll
        for (int j = 0; j < 4; ++j) {
            float4 bv = pb[j];
            float4 sv = ps[j];
            float p0 = bv.x * sv.x, p1 = bv.y * sv.y;
            float p2 = bv.z * sv.z, p3 = bv.w * sv.w;
            float l0, l1, l2, l3;
            u32 h0 = split1(p0, l0), h1 = split1(p1, l1);
            u32 h2 = split1(p2, l2), h3 = split1(p3, l3);
            hw[j * 2 + 0] = h0 | (h1 << 16);
            hw[j * 2 + 1] = h2 | (h3 << 16);
            lw[j * 2 + 0] = bf16rn(l0) | (bf16rn(l1) << 16);
            lw[j * 2 + 1] = bf16rn(l2) | (bf16rn(l3) << 16);
        }
        pBh[0] = make_uint4(hw[0], hw[1], hw[2], hw[3]);
        pBh[1] = make_uint4(hw[4], hw[5], hw[6], hw[7]);
        pBl[0] = make_uint4(lw[0], lw[1], lw[2], lw[3]);
        pBl[1] = make_uint4(lw[4], lw[5], lw[6], lw[7]);
    };

    const int niter = K >> 5;
    load_regs(0);

    for (int it = 0; it < niter; ++it) {
        const u32 stg = sb + (u32)(it & 1) * STAGE_BYTES;
        // store staged regs
        {
            const u32 d = stg + stoff;
            STS128(d,                  pAh[0]); STS128(d + 16,                  pAh[1]);
            STS128(d + MAT_BYTES,      pAl[0]); STS128(d + MAT_BYTES + 16,      pAl[1]);
            STS128(d + 2 * MAT_BYTES,  pBh[0]); STS128(d + 2 * MAT_BYTES + 16,  pBh[1]);
            STS128(d + 3 * MAT_BYTES,  pBl[0]); STS128(d + 3 * MAT_BYTES + 16,  pBl[1]);
        }
        __syncthreads();
        if (it + 1 < niter) load_regs((it + 1) << 5);

        const u32 aH = stg + a_base;
        const u32 aL = stg + MAT_BYTES + a_base;
        const u32 bH = stg + 2 * MAT_BYTES + b_base;
        const u32 bL = stg + 3 * MAT_BYTES + b_base;

        #pragma unroll
        for (int ks = 0; ks < 2; ++ks) {
            u32 Ah[4][4], Al[4][4], Bh[2][4], Bl[2][4];
            #pragma unroll
            for (int mi = 0; mi < 4; ++mi) {
                ldsm4(Ah[mi], aH + mi * (16 * ROWP) + ks * 32);
                ldsm4(Al[mi], aL + mi * (16 * ROWP) + ks * 32);
            }
            #pragma unroll
            for (int jj = 0; jj < 2; ++jj) {
                ldsm4(Bh[jj], bH + jj * (16 * ROWP) + ks * 32);
                ldsm4(Bl[jj], bL + jj * (16 * ROWP) + ks * 32);
            }
            #pragma unroll
            for (int mi = 0; mi < 4; ++mi)
                #pragma unroll
                for (int jj = 0; jj < 2; ++jj) {
                    mma_bf16(acc[mi][2 * jj],     Ah[mi], &Bh[jj][0]);
                    mma_bf16(acc[mi][2 * jj + 1], Ah[mi], &Bh[jj][2]);
                    mma_bf16(acc[mi][2 * jj],     Ah[mi], &Bl[jj][0]);
                    mma_bf16(acc[mi][2 * jj + 1], Ah[mi], &Bl[jj][2]);
                    mma_bf16(acc[mi][2 * jj],     Al[mi], &Bh[jj][0]);
                    mma_bf16(acc[mi][2 * jj + 1], Al[mi], &Bh[jj][2]);
                }
        }
    }

    // ---- epilogue ----
    const int gid = lid >> 2;
    const int tig = lid & 3;
    #pragma unroll
    for (int mi = 0; mi < 4; ++mi) {
        #pragma unroll
        for (int nj = 0; nj < 4; ++nj) {
            const int row = m0 + m0w + 16 * mi + gid;
            const int col = n0 + n0w + 8 * nj + tig * 2;
            const float* a = acc[mi][nj];
            if (OUT_PAIR) {
                size_t o0 = (size_t)b * strideC + (size_t)row * ldc + col;
                size_t o1 = o0 + 8 * ldc;
                float l0, l1, l2, l3;
                u32 h0 = split1(a[0], l0), h1 = split1(a[1], l1);
                u32 h2 = split1(a[2], l2), h3 = split1(a[3], l3);
                *(u32*)(Chi + o0) = h0 | (h1 << 16);
                *(u32*)(Clo + o0) = bf16rn(l0) | (bf16rn(l1) << 16);
                *(u32*)(Chi + o1) = h2 | (h3 << 16);
                *(u32*)(Clo + o1) = bf16rn(l2) | (bf16rn(l3) << 16);
            } else {
                float* d0 = Cf + (size_t)b * strideC + (size_t)row * ldc + col;
                *(float2*)d0            = make_float2(a[0], a[1]);
                *(float2*)(d0 + 8 * ldc) = make_float2(a[2], a[3]);
            }
        }
    }
}

// ---------------- launcher ---------------------------------------------------
extern "C" void kernel_launch(void* const* d_in, const int* in_sizes, int n_in,
                              void* d_out, int out_size) {
    const float* x   = (const float*)d_in[0];
    const float* W1  = (const float*)d_in[1];
    const float* b1  = (const float*)d_in[2];
    const float* W2  = (const float*)d_in[3];
    const float* b2  = (const float*)d_in[4];
    const float* b3  = (const float*)d_in[5];
    const float* b_r = (const float*)d_in[6];

    float* out     = (float*)d_out;
    float* out_rec = out;                           // [128,1024]
    float* out_c2  = out + (size_t)BB * DD;         // [128,256]
    float* out_jac = out_c2 + (size_t)BB * HH2;     // [D, B, D] flat

    float *c1, *s1, *c2, *s2, *c3, *s3, *W2T, *M2;
    __nv_bfloat16 *W1Thi, *W1Tlo, *M1hi, *M1lo;
    cudaGetSymbolAddress((void**)&c1, g_c1);
    cudaGetSymbolAddress((void**)&s1, g_s1);
    cudaGetSymbolAddress((void**)&c2, g_c2);
    cudaGetSymbolAddress((void**)&s2, g_s2);
    cudaGetSymbolAddress((void**)&c3, g_c3);
    cudaGetSymbolAddress((void**)&s3, g_s3);
    cudaGetSymbolAddress((void**)&W2T, g_W2T);
    cudaGetSymbolAddress((void**)&M2, g_M2);
    cudaGetSymbolAddress((void**)&W1Thi, g_W1Thi);
    cudaGetSymbolAddress((void**)&W1Tlo, g_W1Tlo);
    cudaGetSymbolAddress((void**)&M1hi, g_M1hi);
    cudaGetSymbolAddress((void**)&M1lo, g_M1lo);

    cudaFuncSetAttribute(gemm_split<true>,
                         cudaFuncAttributeMaxDynamicSharedMemorySize, SMEM_GEMM_BYTES);
    cudaFuncSetAttribute(gemm_split<false>,
                         cudaFuncAttributeMaxDynamicSharedMemorySize, SMEM_GEMM_BYTES);

    // -------- weight prep (tiny) --------
    transpose_split_k<<<dim3(DD / 32, HH1 / 32), dim3(32, 8)>>>(W1, HH1, DD, W1Thi, W1Tlo);
    transpose_f32_k<<<dim3(HH1 / 32, HH2 / 32), dim3(32, 8)>>>(W2, HH2, HH1, W2T);

    // -------- forward pass --------
    fwd_kernel<<<dim3(HH1 / 128, BB), 128>>>(x,  W1, b1,  c1, s1, nullptr, DD,  HH1, 1);
    fwd_kernel<<<dim3(HH2 / 128, BB), 128>>>(c1, W2, b2,  c2, s2, out_c2,  HH1, HH2, 1);
    fwd_kernel<<<dim3(HH1 / 128, BB), 128>>>(c2, W2, b3,  c3, s3, nullptr, HH2, HH1, 0);
    fwd_kernel<<<dim3(DD  / 128, BB), 128>>>(c3, W1, b_r, out_rec, nullptr, nullptr, HH1, DD, 0);

    // -------- Jacobian chain on tensor cores (HMMA split-bf16) --------
    // GEMM A: M1'[b][d,e] = sum_h W1T[d,h]*s3[b,h]*W2[e,h]   -> bf16 pair out
    gemm_split<true><<<dim3(HH2 / 128, DD / 128, BB), 256, SMEM_GEMM_BYTES>>>(
        W1Thi, W1Tlo, 0,
        W2, 0,
        s3, HH1,
        nullptr, M1hi, M1lo,
        (size_t)HH2, (size_t)DD * HH2);

    // GEMM B: M2'[b][d,h] = sum_e M1'[d,e]*s2[b,e]*W2T[h,e]  -> fp32 out
    gemm_split<false><<<dim3(HH1 / 128, DD / 128, BB), 256, SMEM_GEMM_BYTES>>>(
        M1hi, M1lo, (size_t)DD * HH2,
        W2T, 0,
        s2, HH2,
        M2, nullptr, nullptr,
        (size_t)HH1, (size_t)DD * HH1);

    // GEMM C: Jac[b][d,e'] = sum_h W1T[d,h]*s1[b,h]*M2'[e',h] -> fp32 to d_out
    // flat offset(b,d,e') = d*(B*D) + b*D + e'  => ldc = B*D, strideC = D
    gemm_split<false><<<dim3(DD / 128, DD / 128, BB), 256, SMEM_GEMM_BYTES>>>(
        W1Thi, W1Tlo, 0,
        M2, (size_t)DD * HH1,
        s1, HH1,
        out_jac, nullptr, nullptr,
        (size_t)BB * DD, (size_t)DD);
}

// round 4
// speedup vs baseline: 4.7417x; 1.6228x over previous
#include <cuda_runtime.h>
#include <cuda_bf16.h>
#include <cstdint>

#define BB   128
#define DD   1024
#define HH1  512
#define HH2  256

typedef unsigned int u32;
typedef unsigned long long u64;

// ---------------- scratch (device globals; no allocation allowed) ----------
__device__ float g_c1[BB * HH1];
__device__ float g_s1[BB * HH1];
__device__ float g_c2[BB * HH2];
__device__ float g_s2[BB * HH2];
__device__ float g_c3[BB * HH1];
__device__ float g_s3[BB * HH1];
__device__ __nv_bfloat16 g_W1Thi[DD * HH1];              // W1^T hi  [1024,512]
__device__ __nv_bfloat16 g_W1Tlo[DD * HH1];              // W1^T lo
__device__ __nv_bfloat16 g_M1hi[(size_t)BB * DD * HH2];  // R' pair [b][1024,256]
__device__ __nv_bfloat16 g_M1lo[(size_t)BB * DD * HH2];
__device__ __nv_bfloat16 g_Lhi[(size_t)BB * DD * HH2];   // L pair  [b][1024,256]
__device__ __nv_bfloat16 g_Llo[(size_t)BB * DD * HH2];

// ---------------- helpers ----------------------------------------------------
__device__ __forceinline__ u32 smem_u32(const void* p) {
    u32 a;
    asm("{ .reg .u64 t; cvta.to.shared.u64 t, %1; cvt.u32.u64 %0, t; }"
        : "=r"(a) : "l"(p));
    return a;
}

#define STS128(ad, v) \
    asm volatile("st.shared.v4.b32 [%0], {%1, %2, %3, %4};" \
                 :: "r"(ad), "r"((v).x), "r"((v).y), "r"((v).z), "r"((v).w) : "memory")

__device__ __forceinline__ void ldsm4(u32* r, u32 addr) {
    asm volatile("ldmatrix.sync.aligned.m8n8.x4.shared.b16 {%0,%1,%2,%3}, [%4];"
                 : "=r"(r[0]), "=r"(r[1]), "=r"(r[2]), "=r"(r[3]) : "r"(addr));
}

__device__ __forceinline__ void mma_bf16(float* c, const u32* a, const u32* b) {
    asm volatile("mma.sync.aligned.m16n8k16.row.col.f32.bf16.bf16.f32 "
                 "{%0,%1,%2,%3}, {%4,%5,%6,%7}, {%8,%9}, {%0,%1,%2,%3};"
                 : "+f"(c[0]), "+f"(c[1]), "+f"(c[2]), "+f"(c[3])
                 : "r"(a[0]), "r"(a[1]), "r"(a[2]), "r"(a[3]),
                   "r"(b[0]), "r"(b[1]));
}

// bf16 split: hi = rn(p) (bf16 bits), lo = p - hi (exact fp32)
__device__ __forceinline__ u32 split1(float p, float& lo) {
    u32 u = __float_as_uint(p);
    u32 r = (u + 0x7FFFu + ((u >> 16) & 1u)) & 0xFFFF0000u;
    lo = p - __uint_as_float(r);
    return r >> 16;
}
__device__ __forceinline__ u32 bf16rn(float p) {
    u32 u = __float_as_uint(p);
    return (u + 0x7FFFu + ((u >> 16) & 1u)) >> 16;
}

// ---------------- forward pass -----------------------------------------------
// 4 threads per output (K split 4 ways, shfl reduce). grid (N/32, B), 128 thr.
__global__ void fwd_kernel(const float* __restrict__ A,
                           const float* __restrict__ W,
                           const float* __restrict__ bias,
                           float* __restrict__ c_out,
                           float* __restrict__ s_out,
                           float* __restrict__ extra_out,
                           int K, int N, int transW) {
    __shared__ float sA[1024];
    const int b   = blockIdx.y;
    const int tid = threadIdx.x;
    {
        const float4* src = (const float4*)(A + (size_t)b * K);
        float4* dst = (float4*)sA;
        for (int k = tid; k < (K >> 2); k += 128) dst[k] = src[k];
    }
    __syncthreads();
    const int on = tid >> 2, kq = tid & 3;
    const int n  = blockIdx.x * 32 + on;
    const int kpt = K >> 2;
    const int k0  = kq * kpt;
    float a0 = 0.f, a1 = 0.f, a2 = 0.f, a3 = 0.f;
    if (transW) {
        const float* wr = W + (size_t)n * K + k0;
        const float* ar = sA + k0;
        #pragma unroll 4
        for (int k = 0; k < kpt; k += 4) {
            float4 w4 = *(const float4*)(wr + k);
            float4 x4 = *(const float4*)(ar + k);
            a0 += x4.x * w4.x; a1 += x4.y * w4.y;
            a2 += x4.z * w4.z; a3 += x4.w * w4.w;
        }
    } else {
        #pragma unroll 4
        for (int k = 0; k < kpt; k += 4) {
            a0 += sA[k0 + k]     * W[(size_t)(k0 + k) * N + n];
            a1 += sA[k0 + k + 1] * W[(size_t)(k0 + k + 1) * N + n];
            a2 += sA[k0 + k + 2] * W[(size_t)(k0 + k + 2) * N + n];
            a3 += sA[k0 + k + 3] * W[(size_t)(k0 + k + 3) * N + n];
        }
    }
    float acc = (a0 + a1) + (a2 + a3);
    acc += __shfl_xor_sync(0xFFFFFFFFu, acc, 1);
    acc += __shfl_xor_sync(0xFFFFFFFFu, acc, 2);
    if (kq == 0) {
        acc += bias[n];
        const float c = 1.0f / (1.0f + expf(-acc));
        if (c_out)     c_out[(size_t)b * N + n]     = c;
        if (s_out)     s_out[(size_t)b * N + n]     = c * (1.0f - c);
        if (extra_out) extra_out[(size_t)b * N + n] = c;
    }
}

// ---------------- one-time transpose+split of W1 -----------------------------
__global__ void transpose_split_k(const float* __restrict__ in, int R, int C,
                                  __nv_bfloat16* __restrict__ oh,
                                  __nv_bfloat16* __restrict__ ol) {
    __shared__ float t[32][33];
    const int c0 = blockIdx.x * 32, r0 = blockIdx.y * 32;
    const int tx = threadIdx.x, ty = threadIdx.y;
    #pragma unroll
    for (int i = 0; i < 32; i += 8)
        t[ty + i][tx] = in[(size_t)(r0 + ty + i) * C + c0 + tx];
    __syncthreads();
    #pragma unroll
    for (int i = 0; i < 32; i += 8) {
        float v = t[tx][ty + i];
        size_t o = (size_t)(c0 + ty + i) * R + r0 + tx;
        float lf; u32 h = split1(v, lf);
        ((unsigned short*)oh)[o] = (unsigned short)h;
        ((unsigned short*)ol)[o] = (unsigned short)bf16rn(lf);
    }
}

// ---------------- HMMA split-bf16 batched GEMM -------------------------------
// out[b][m, n] = sum_k A[b][m,k] * (loader scale) * B[b][n,k]
// A: bf16 hi/lo pair. B: fp32 + scale-split (B_PAIR=0) or bf16 pair (B_PAIR=1).
// EPI_SCALE: multiply result by episc[b, n] in epilogue (before pair split).
// OUT_PAIR: store bf16 hi/lo pair; else fp32.
#define ROWP        80
#define MAT_BYTES   (128 * ROWP)
#define STAGE_BYTES (4 * MAT_BYTES)
#define SMEM_GEMM_BYTES (2 * STAGE_BYTES)

template <bool OUT_PAIR, bool B_PAIR, bool EPI_SCALE>
__global__ void __launch_bounds__(256)
gemm_split(const __nv_bfloat16* __restrict__ Ahi_g,
           const __nv_bfloat16* __restrict__ Alo_g, size_t strideA,
           const float* __restrict__ Bf_g,
           const __nv_bfloat16* __restrict__ Bhi_g,
           const __nv_bfloat16* __restrict__ Blo_g, size_t strideB,
           const float* __restrict__ sc_g, int K,
           const float* __restrict__ episc_g, int epiN,
           float* __restrict__ Cf,
           __nv_bfloat16* __restrict__ Chi, __nv_bfloat16* __restrict__ Clo,
           size_t ldc, size_t strideC) {
    extern __shared__ char smem[];
    const u32 sb  = smem_u32(smem);
    const int tid = threadIdx.x;
    const int wid = tid >> 5;
    const int lid = tid & 31;
    const int b   = blockIdx.z;
    const int n0  = blockIdx.x * 128;
    const int m0  = blockIdx.y * 128;

    const int m0w = (wid & 1) * 64;
    const int n0w = (wid >> 1) * 32;

    const __nv_bfloat16* Ahi_b = Ahi_g + (size_t)b * strideA;
    const __nv_bfloat16* Alo_b = Alo_g + (size_t)b * strideA;

    const int r  = tid >> 1;
    const int hs = tid & 1;
    const size_t aRow = (size_t)(m0 + r) * K;
    const size_t bRow = (size_t)(n0 + r) * K;
    const u32 stoff = (u32)r * ROWP + (u32)hs * 32;

    const int l = lid;
    const u32 a_base = (u32)((m0w + (l & 7) + ((l >> 3) & 1) * 8) * ROWP
                             + ((l >> 4) & 1) * 16);
    const int mt = l >> 3;
    const u32 b_base = (u32)((n0w + ((mt >> 1) & 1) * 8 + (l & 7)) * ROWP
                             + (mt & 1) * 16);

    float acc[4][4][4];
    #pragma unroll
    for (int i = 0; i < 4; i++)
        #pragma unroll
        for (int j = 0; j < 4; j++)
            #pragma unroll
            for (int q = 0; q < 4; q++) acc[i][j][q] = 0.f;

    uint4 pAh[2], pAl[2], pBh[2], pBl[2];

    auto load_regs = [&](int kt) {
        {
            const uint4* ph = (const uint4*)(Ahi_b + aRow + kt) + hs * 2;
            const uint4* pl = (const uint4*)(Alo_b + aRow + kt) + hs * 2;
            pAh[0] = ph[0]; pAh[1] = ph[1];
            pAl[0] = pl[0]; pAl[1] = pl[1];
        }
        if (B_PAIR) {
            const uint4* ph = (const uint4*)(Bhi_g + (size_t)b * strideB + bRow + kt) + hs * 2;
            const uint4* pl = (const uint4*)(Blo_g + (size_t)b * strideB + bRow + kt) + hs * 2;
            pBh[0] = ph[0]; pBh[1] = ph[1];
            pBl[0] = pl[0]; pBl[1] = pl[1];
        } else {
            const float4* pb = (const float4*)(Bf_g + (size_t)b * strideB + bRow + kt) + hs * 4;
            const float4* ps = (const float4*)(sc_g + (size_t)b * K + kt) + hs * 4;
            u32 hw[8], lw[8];
            #pragma unroll
            for (int j = 0; j < 4; ++j) {
                float4 bv = pb[j];
                float4 sv = ps[j];
                float p0 = bv.x * sv.x, p1 = bv.y * sv.y;
                float p2 = bv.z * sv.z, p3 = bv.w * sv.w;
                float l0, l1, l2, l3;
                u32 h0 = split1(p0, l0), h1 = split1(p1, l1);
                u32 h2 = split1(p2, l2), h3 = split1(p3, l3);
                hw[j * 2 + 0] = h0 | (h1 << 16);
                hw[j * 2 + 1] = h2 | (h3 << 16);
                lw[j * 2 + 0] = bf16rn(l0) | (bf16rn(l1) << 16);
                lw[j * 2 + 1] = bf16rn(l2) | (bf16rn(l3) << 16);
            }
            pBh[0] = make_uint4(hw[0], hw[1], hw[2], hw[3]);
            pBh[1] = make_uint4(hw[4], hw[5], hw[6], hw[7]);
            pBl[0] = make_uint4(lw[0], lw[1], lw[2], lw[3]);
            pBl[1] = make_uint4(lw[4], lw[5], lw[6], lw[7]);
        }
    };

    const int niter = K >> 5;
    load_regs(0);

    for (int it = 0; it < niter; ++it) {
        const u32 stg = sb + (u32)(it & 1) * STAGE_BYTES;
        {
            const u32 d = stg + stoff;
            STS128(d,                  pAh[0]); STS128(d + 16,                  pAh[1]);
            STS128(d + MAT_BYTES,      pAl[0]); STS128(d + MAT_BYTES + 16,      pAl[1]);
            STS128(d + 2 * MAT_BYTES,  pBh[0]); STS128(d + 2 * MAT_BYTES + 16,  pBh[1]);
            STS128(d + 3 * MAT_BYTES,  pBl[0]); STS128(d + 3 * MAT_BYTES + 16,  pBl[1]);
        }
        __syncthreads();
        if (it + 1 < niter) load_regs((it + 1) << 5);

        const u32 aH = stg + a_base;
        const u32 aL = stg + MAT_BYTES + a_base;
        const u32 bH = stg + 2 * MAT_BYTES + b_base;
        const u32 bL = stg + 3 * MAT_BYTES + b_base;

        #pragma unroll
        for (int ks = 0; ks < 2; ++ks) {
            u32 Ah[4][4], Al[4][4], Bh[2][4], Bl[2][4];
            #pragma unroll
            for (int mi = 0; mi < 4; ++mi) {
                ldsm4(Ah[mi], aH + mi * (16 * ROWP) + ks * 32);
                ldsm4(Al[mi], aL + mi * (16 * ROWP) + ks * 32);
            }
            #pragma unroll
            for (int jj = 0; jj < 2; ++jj) {
                ldsm4(Bh[jj], bH + jj * (16 * ROWP) + ks * 32);
                ldsm4(Bl[jj], bL + jj * (16 * ROWP) + ks * 32);
            }
            #pragma unroll
            for (int mi = 0; mi < 4; ++mi)
                #pragma unroll
                for (int jj = 0; jj < 2; ++jj) {
                    mma_bf16(acc[mi][2 * jj],     Ah[mi], &Bh[jj][0]);
                    mma_bf16(acc[mi][2 * jj + 1], Ah[mi], &Bh[jj][2]);
                    mma_bf16(acc[mi][2 * jj],     Ah[mi], &Bl[jj][0]);
                    mma_bf16(acc[mi][2 * jj + 1], Ah[mi], &Bl[jj][2]);
                    mma_bf16(acc[mi][2 * jj],     Al[mi], &Bh[jj][0]);
                    mma_bf16(acc[mi][2 * jj + 1], Al[mi], &Bh[jj][2]);
                }
        }
    }

    // ---- epilogue ----
    const int gid = lid >> 2;
    const int tig = lid & 3;
    #pragma unroll
    for (int mi = 0; mi < 4; ++mi) {
        #pragma unroll
        for (int nj = 0; nj < 4; ++nj) {
            const int row = m0 + m0w + 16 * mi + gid;
            const int col = n0 + n0w + 8 * nj + tig * 2;
            float a[4] = { acc[mi][nj][0], acc[mi][nj][1],
                           acc[mi][nj][2], acc[mi][nj][3] };
            if (EPI_SCALE) {
                const float* es = episc_g + (size_t)b * epiN + col;
                const float s0 = es[0], s1 = es[1];
                a[0] *= s0; a[1] *= s1; a[2] *= s0; a[3] *= s1;
            }
            if (OUT_PAIR) {
                size_t o0 = (size_t)b * strideC + (size_t)row * ldc + col;
                size_t o1 = o0 + 8 * ldc;
                float l0, l1, l2, l3;
                u32 h0 = split1(a[0], l0), h1 = split1(a[1], l1);
                u32 h2 = split1(a[2], l2), h3 = split1(a[3], l3);
                *(u32*)(Chi + o0) = h0 | (h1 << 16);
                *(u32*)(Clo + o0) = bf16rn(l0) | (bf16rn(l1) << 16);
                *(u32*)(Chi + o1) = h2 | (h3 << 16);
                *(u32*)(Clo + o1) = bf16rn(l2) | (bf16rn(l3) << 16);
            } else {
                float* d0 = Cf + (size_t)b * strideC + (size_t)row * ldc + col;
                *(float2*)d0             = make_float2(a[0], a[1]);
                *(float2*)(d0 + 8 * ldc) = make_float2(a[2], a[3]);
            }
        }
    }
}

// ---------------- launcher ---------------------------------------------------
extern "C" void kernel_launch(void* const* d_in, const int* in_sizes, int n_in,
                              void* d_out, int out_size) {
    const float* x   = (const float*)d_in[0];
    const float* W1  = (const float*)d_in[1];
    const float* b1  = (const float*)d_in[2];
    const float* W2  = (const float*)d_in[3];
    const float* b2  = (const float*)d_in[4];
    const float* b3  = (const float*)d_in[5];
    const float* b_r = (const float*)d_in[6];

    float* out     = (float*)d_out;
    float* out_rec = out;                           // [128,1024]
    float* out_c2  = out + (size_t)BB * DD;         // [128,256]
    float* out_jac = out_c2 + (size_t)BB * HH2;     // [D, B, D] flat

    float *c1, *s1, *c2, *s2, *c3, *s3;
    __nv_bfloat16 *W1Thi, *W1Tlo, *M1hi, *M1lo, *Lhi, *Llo;
    cudaGetSymbolAddress((void**)&c1, g_c1);
    cudaGetSymbolAddress((void**)&s1, g_s1);
    cudaGetSymbolAddress((void**)&c2, g_c2);
    cudaGetSymbolAddress((void**)&s2, g_s2);
    cudaGetSymbolAddress((void**)&c3, g_c3);
    cudaGetSymbolAddress((void**)&s3, g_s3);
    cudaGetSymbolAddress((void**)&W1Thi, g_W1Thi);
    cudaGetSymbolAddress((void**)&W1Tlo, g_W1Tlo);
    cudaGetSymbolAddress((void**)&M1hi, g_M1hi);
    cudaGetSymbolAddress((void**)&M1lo, g_M1lo);
    cudaGetSymbolAddress((void**)&Lhi, g_Lhi);
    cudaGetSymbolAddress((void**)&Llo, g_Llo);

    cudaFuncSetAttribute(gemm_split<true, false, false>,
                         cudaFuncAttributeMaxDynamicSharedMemorySize, SMEM_GEMM_BYTES);
    cudaFuncSetAttribute(gemm_split<true, false, true>,
                         cudaFuncAttributeMaxDynamicSharedMemorySize, SMEM_GEMM_BYTES);
    cudaFuncSetAttribute(gemm_split<false, true, false>,
                         cudaFuncAttributeMaxDynamicSharedMemorySize, SMEM_GEMM_BYTES);

    // -------- weight prep (tiny) --------
    transpose_split_k<<<dim3(DD / 32, HH1 / 32), dim3(32, 8)>>>(W1, HH1, DD, W1Thi, W1Tlo);

    // -------- forward pass --------
    fwd_kernel<<<dim3(HH1 / 32, BB), 128>>>(x,  W1, b1,  c1, s1, nullptr, DD,  HH1, 1);
    fwd_kernel<<<dim3(HH2 / 32, BB), 128>>>(c1, W2, b2,  c2, s2, out_c2,  HH1, HH2, 1);
    fwd_kernel<<<dim3(HH1 / 32, BB), 128>>>(c2, W2, b3,  c3, s3, nullptr, HH2, HH1, 0);
    fwd_kernel<<<dim3(DD  / 32, BB), 128>>>(c3, W1, b_r, out_rec, nullptr, nullptr, HH1, DD, 0);

    // -------- Jacobian chain on tensor cores (HMMA split-bf16) --------
    // GEMM A1: M1[b][d',e] = sum_h W1T[d',h]*s3[b,h]*W2[e,h]  -> bf16 pair
    gemm_split<true, false, false><<<dim3(HH2 / 128, DD / 128, BB), 256, SMEM_GEMM_BYTES>>>(
        W1Thi, W1Tlo, 0,
        W2, nullptr, nullptr, 0,
        s3, HH1,
        nullptr, 0,
        nullptr, M1hi, M1lo,
        (size_t)HH2, (size_t)DD * HH2);

    // GEMM A2: L[b][d,e] = (sum_h W1T[d,h]*s1[b,h]*W2[e,h]) * s2[b,e] -> pair
    gemm_split<true, false, true><<<dim3(HH2 / 128, DD / 128, BB), 256, SMEM_GEMM_BYTES>>>(
        W1Thi, W1Tlo, 0,
        W2, nullptr, nullptr, 0,
        s1, HH1,
        s2, HH2,
        nullptr, Lhi, Llo,
        (size_t)HH2, (size_t)DD * HH2);

    // GEMM C': Jac[b][d,d'] = sum_e L[b][d,e] * M1[b][d',e]  (K=256, both pairs)
    // flat offset(b,d,d') = d*(B*D) + b*D + d'  => ldc = B*D, strideC = D
    gemm_split<false, true, false><<<dim3(DD / 128, DD / 128, BB), 256, SMEM_GEMM_BYTES>>>(
        Lhi, Llo, (size_t)DD * HH2,
        nullptr, M1hi, M1lo, (size_t)DD * HH2,
        nullptr, HH2,
        nullptr, 0,
        out_jac, nullptr, nullptr,
        (size_t)BB * DD, (size_t)DD);
}